// round 16
// baseline (speedup 1.0000x reference)
#include <cuda_runtime.h>

#define D_IN   187
#define H_HID  50
#define C_OUT  5
#define LPR    4            // lanes per row-group
#define HP     13           // h per lane (52 padded)
#define TPB    128
#define RPB    64           // rows per block (2 rows per lane group)
#define DCH    48           // d-chunk (4 chunks: 48*3 + 43)
#define SXP    52           // sx row pitch: 16B-aligned, bases mod 32 distinct
#define THR    1.0f
#define BETA   0.9f

typedef unsigned long long u64;

// packed f32x2 helpers (two independent RN fp32 ops -> bit-identical to scalar)
#define FMA2(acc, s, w) asm("fma.rn.f32x2 %0, %1, %2, %0;" : "+l"(acc) : "l"(s), "l"(w))
#define DUP2(d, f)      asm("mov.b64 %0, {%1, %1};" : "=l"(d) : "f"(f))
#define UNPK2(lo, hi, d) asm("mov.b64 {%0, %1}, %2;" : "=f"(lo), "=f"(hi) : "l"(d))

// Predicated two-timestep LIF update + conditional accumulates.
// Bit-identical to: r0=(m>1); m1=fsub(fma(.9,m,c1),r0); s1=(m1>1);
// m2=fsub(fma(.9,m1,c1),s1); s2=(m2>1); acc{A,B} += s{1,2}*w.
// (pred-off sub == fsub(x,0); pred-off add == fma(0,w,acc); acc never -0)
#define STEP2(m, a01A, a23A, a4A, a01B, a23B, a4B, c1, w01, w23, w4)  \
    asm("{\n\t"                                                       \
        ".reg .pred p0, p1, p2;\n\t"                                  \
        ".reg .f32 t;\n\t"                                            \
        "setp.gt.f32 p0, %0, 0f3F800000;\n\t"                         \
        "fma.rn.f32 t, 0f3F666666, %0, %7;\n\t"                       \
        "@p0 sub.rn.f32 t, t, 0f3F800000;\n\t"                        \
        "setp.gt.f32 p1, t, 0f3F800000;\n\t"                          \
        "fma.rn.f32 %0, 0f3F666666, t, %7;\n\t"                       \
        "@p1 sub.rn.f32 %0, %0, 0f3F800000;\n\t"                      \
        "setp.gt.f32 p2, %0, 0f3F800000;\n\t"                         \
        "@p1 add.rn.f32x2 %1, %1, %8;\n\t"                            \
        "@p1 add.rn.f32x2 %2, %2, %9;\n\t"                            \
        "@p1 add.rn.f32 %3, %3, %10;\n\t"                             \
        "@p2 add.rn.f32x2 %4, %4, %8;\n\t"                            \
        "@p2 add.rn.f32x2 %5, %5, %9;\n\t"                            \
        "@p2 add.rn.f32 %6, %6, %10;\n\t"                             \
        "}"                                                           \
        : "+f"(m), "+l"(a01A), "+l"(a23A), "+f"(a4A),                 \
          "+l"(a01B), "+l"(a23B), "+f"(a4B)                           \
        : "f"(c1), "l"(w01), "l"(w23), "f"(w4))

// Shared layout (floats):
//  sW1: [dloc][j*20+i] pitch 80/d; lane 128b bases {0,20,8,28} mod 32 conflict-free
//  sW2: [h][8] (h padded to 52); per-hh 16B loads at h*32B -> conflict-free
//  sx : [r][SXP], r in 0..63
#define SM_W1   0
#define SM_W1_SZ (DCH * 80)              // 3840
#define SM_W2   (SM_W1 + SM_W1_SZ)
#define SM_W2_SZ (52 * 8)                // 416
#define SM_X    (SM_W2 + SM_W2_SZ)
#define SM_X_SZ (RPB * SXP)              // 3328
#define SMEM_BYTES ((SM_X + SM_X_SZ) * 4)   // 30336 B -> 4 blocks/SM

__global__ __launch_bounds__(TPB, 4)
void snn_fused_kernel(const float* __restrict__ x,
                      const float* __restrict__ W1,
                      const float* __restrict__ b1,
                      const float* __restrict__ W2,
                      const float* __restrict__ b2,
                      float* __restrict__ out,
                      int B, int steps)
{
    extern __shared__ float smem[];
    float* sW1 = smem + SM_W1;
    float* sW2 = smem + SM_W2;
    float* sx  = smem + SM_X;

    const int tid   = threadIdx.x;
    const int j     = tid & (LPR - 1);
    const int rloc  = tid >> 2;                 // 0..31
    const int rowA  = blockIdx.x * RPB + rloc;
    const int rowB  = rowA + 32;
    const bool vA   = (rowA < B);
    const bool vB   = (rowB < B);
    const int hbase = j * HP;

    // ---- stage W2 [h][8], h>=50 zero ----
    for (int idx = tid; idx < 52 * C_OUT; idx += TPB) {
        int h = idx % 52, c = idx / 52;
        sW2[h * 8 + c] = (h < H_HID) ? W2[c * H_HID + h] : 0.0f;
    }

    // ---- phase 1: cur1 for BOTH rows; exact ascending-k fma chains (f32x2) ----
    u64 A01a = 0, A23a = 0, A45a = 0, A67a = 0, A89a = 0, Aaba = 0;
    u64 A01b = 0, A23b = 0, A45b = 0, A67b = 0, A89b = 0, Aabb = 0;
    float a12a = 0.0f, a12b = 0.0f;

    for (int d0 = 0; d0 < D_IN; d0 += DCH) {
        const int len = (D_IN - d0 < DCH) ? (D_IN - d0) : DCH;
        __syncthreads();
        for (int idx = tid; idx < 52 * len; idx += TPB) {
            int h = idx % 52, dloc = idx / 52;
            float v = (h < H_HID) ? W1[h * D_IN + d0 + dloc] : 0.0f;
            sW1[dloc * 80 + (h / HP) * 20 + (h % HP)] = v;
        }
        for (int i2 = tid; i2 < RPB * len; i2 += TPB) {
            int r  = i2 / len;
            int dl = i2 - r * len;
            int gr = blockIdx.x * RPB + r;
            sx[r * SXP + dl] = (gr < B) ? x[(size_t)gr * D_IN + d0 + dl] : 0.0f;
        }
        __syncthreads();
        const float* xA = &sx[rloc * SXP];
        const float* xB = &sx[(rloc + 32) * SXP];
        const float* wbase = &sW1[j * 20];

#define GEMM_BODY(XVA, XVB, DL) do {                                      \
            const float* wp = wbase + (DL) * 80;                          \
            ulonglong2 wA = *(const ulonglong2*)(wp);                     \
            ulonglong2 wB = *(const ulonglong2*)(wp + 4);                 \
            ulonglong2 wC = *(const ulonglong2*)(wp + 8);                 \
            float w12 = wp[12];                                           \
            u64 xda; DUP2(xda, (XVA));                                    \
            u64 xdb; DUP2(xdb, (XVB));                                    \
            FMA2(A01a, xda, wA.x); FMA2(A23a, xda, wA.y);                 \
            FMA2(A45a, xda, wB.x); FMA2(A67a, xda, wB.y);                 \
            FMA2(A89a, xda, wC.x); FMA2(Aaba, xda, wC.y);                 \
            a12a = fmaf(w12, (XVA), a12a);                                \
            FMA2(A01b, xdb, wA.x); FMA2(A23b, xdb, wA.y);                 \
            FMA2(A45b, xdb, wB.x); FMA2(A67b, xdb, wB.y);                 \
            FMA2(A89b, xdb, wC.x); FMA2(Aabb, xdb, wC.y);                 \
            a12b = fmaf(w12, (XVB), a12b);                                \
        } while (0)

        const int q4 = len >> 2;
        const float4* xqA = (const float4*)xA;
        const float4* xqB = (const float4*)xB;
        for (int g = 0; g < q4; ++g) {
            float4 va = xqA[g];
            float4 vb = xqB[g];
            GEMM_BODY(va.x, vb.x, 4 * g + 0);
            GEMM_BODY(va.y, vb.y, 4 * g + 1);
            GEMM_BODY(va.z, vb.z, 4 * g + 2);
            GEMM_BODY(va.w, vb.w, 4 * g + 3);
        }
        for (int dl = q4 * 4; dl < len; ++dl) {
            GEMM_BODY(xA[dl], xB[dl], dl);
        }
#undef GEMM_BODY
    }

    // unpack; bias as separate rounded add; pad h -> 0
    float cur1A[HP], cur1B[HP];
    UNPK2(cur1A[0],  cur1A[1],  A01a); UNPK2(cur1A[2],  cur1A[3],  A23a);
    UNPK2(cur1A[4],  cur1A[5],  A45a); UNPK2(cur1A[6],  cur1A[7],  A67a);
    UNPK2(cur1A[8],  cur1A[9],  A89a); UNPK2(cur1A[10], cur1A[11], Aaba);
    cur1A[12] = a12a;
    UNPK2(cur1B[0],  cur1B[1],  A01b); UNPK2(cur1B[2],  cur1B[3],  A23b);
    UNPK2(cur1B[4],  cur1B[5],  A45b); UNPK2(cur1B[6],  cur1B[7],  A67b);
    UNPK2(cur1B[8],  cur1B[9],  A89b); UNPK2(cur1B[10], cur1B[11], Aabb);
    cur1B[12] = a12b;
#pragma unroll
    for (int i = 0; i < HP; ++i) {
        int h = hbase + i;
        cur1A[i] = (h < H_HID) ? __fadd_rn(cur1A[i], b1[h]) : 0.0f;
        cur1B[i] = (h < H_HID) ? __fadd_rn(cur1B[i], b1[h]) : 0.0f;
    }

    // ---- phase 2: pair-relay over 2 rows (lane j handles pair p = i - j;
    // t = 2p, 2p+1). Each t's 50-term cur2 chain stays exactly serial across
    // lanes (shfl relay). Inner update fully predicated (STEP2 asm).
    float m1A[HP], m1B[HP];
#pragma unroll
    for (int i = 0; i < HP; ++i) { m1A[i] = 0.0f; m1B[i] = 0.0f; }

    u64 PA01a = 0, PA23a = 0, PB01a = 0, PB23a = 0;   // row A, steps t1/t2
    u64 PA01b = 0, PA23b = 0, PB01b = 0, PB23b = 0;   // row B
    float PA4a = 0, PB4a = 0, PA4b = 0, PB4b = 0;

    float mem2A[C_OUT], mem2B[C_OUT], rb2[C_OUT];
#pragma unroll
    for (int c = 0; c < C_OUT; ++c) { mem2A[c] = 0.0f; mem2B[c] = 0.0f; rb2[c] = b2[c]; }

    const size_t memoff = (size_t)steps * B * C_OUT;
    const size_t bstr   = (size_t)B * C_OUT;
    const int npairs = (steps + 1) >> 1;
    const int iters  = npairs + LPR - 1;
    const bool storer = (j == LPR - 1);
    const float* w2p = &sW2[hbase * 8];

    for (int i = 0; i < iters; ++i) {
        u64 qA01a = __shfl_up_sync(0xFFFFFFFFu, PA01a, 1, LPR);
        u64 qA23a = __shfl_up_sync(0xFFFFFFFFu, PA23a, 1, LPR);
        u64 qB01a = __shfl_up_sync(0xFFFFFFFFu, PB01a, 1, LPR);
        u64 qB23a = __shfl_up_sync(0xFFFFFFFFu, PB23a, 1, LPR);
        float qA4a = __shfl_up_sync(0xFFFFFFFFu, PA4a, 1, LPR);
        float qB4a = __shfl_up_sync(0xFFFFFFFFu, PB4a, 1, LPR);
        u64 qA01b = __shfl_up_sync(0xFFFFFFFFu, PA01b, 1, LPR);
        u64 qA23b = __shfl_up_sync(0xFFFFFFFFu, PA23b, 1, LPR);
        u64 qB01b = __shfl_up_sync(0xFFFFFFFFu, PB01b, 1, LPR);
        u64 qB23b = __shfl_up_sync(0xFFFFFFFFu, PB23b, 1, LPR);
        float qA4b = __shfl_up_sync(0xFFFFFFFFu, PA4b, 1, LPR);
        float qB4b = __shfl_up_sync(0xFFFFFFFFu, PB4b, 1, LPR);

        const int p = i - j;
        if ((unsigned)p < (unsigned)npairs) {
            const bool z = (j == 0);
            u64 aA01a = z ? 0 : qA01a, aA23a = z ? 0 : qA23a;
            u64 aB01a = z ? 0 : qB01a, aB23a = z ? 0 : qB23a;
            u64 aA01b = z ? 0 : qA01b, aA23b = z ? 0 : qA23b;
            u64 aB01b = z ? 0 : qB01b, aB23b = z ? 0 : qB23b;
            float aA4a = z ? 0.0f : qA4a, aB4a = z ? 0.0f : qB4a;
            float aA4b = z ? 0.0f : qA4b, aB4b = z ? 0.0f : qB4b;

#pragma unroll
            for (int hh = 0; hh < HP; ++hh) {
                const ulonglong2 wp2 = *(const ulonglong2*)(w2p + hh * 8);
                const float w4 = w2p[hh * 8 + 4];
                STEP2(m1A[hh], aA01a, aA23a, aA4a, aB01a, aB23a, aB4a,
                      cur1A[hh], wp2.x, wp2.y, w4);
                STEP2(m1B[hh], aA01b, aA23b, aA4b, aB01b, aB23b, aB4b,
                      cur1B[hh], wp2.x, wp2.y, w4);
            }
            PA01a = aA01a; PA23a = aA23a; PB01a = aB01a; PB23a = aB23a;
            PA4a = aA4a; PB4a = aB4a;
            PA01b = aA01b; PA23b = aA23b; PB01b = aB01b; PB23b = aB23b;
            PA4b = aA4b; PB4b = aB4b;

            if (storer) {
                const int t1 = 2 * p;
                const int t2 = t1 + 1;
                const bool hasB = (t2 < steps);
                float F[2 * C_OUT];

                if (vA) {
                    UNPK2(F[0], F[1], PA01a); UNPK2(F[2], F[3], PA23a); F[4] = PA4a;
                    UNPK2(F[5], F[6], PB01a); UNPK2(F[7], F[8], PB23a); F[9] = PB4a;
                    const size_t ob1 = (size_t)t1 * bstr + (size_t)rowA * C_OUT;
#pragma unroll
                    for (int c = 0; c < C_OUT; ++c) {
                        const float cur2 = __fadd_rn(F[c], rb2[c]);
                        float m2 = mem2A[c];
                        const float r2 = (m2 > THR) ? 1.0f : 0.0f;
                        m2 = __fsub_rn(fmaf(BETA, m2, cur2), r2);
                        mem2A[c] = m2;
                        out[ob1 + c]          = (m2 > THR) ? 1.0f : 0.0f;
                        out[memoff + ob1 + c] = m2;
                    }
                    if (hasB) {
                        const size_t ob2 = ob1 + bstr;
#pragma unroll
                        for (int c = 0; c < C_OUT; ++c) {
                            const float cur2 = __fadd_rn(F[5 + c], rb2[c]);
                            float m2 = mem2A[c];
                            const float r2 = (m2 > THR) ? 1.0f : 0.0f;
                            m2 = __fsub_rn(fmaf(BETA, m2, cur2), r2);
                            mem2A[c] = m2;
                            out[ob2 + c]          = (m2 > THR) ? 1.0f : 0.0f;
                            out[memoff + ob2 + c] = m2;
                        }
                    }
                }
                if (vB) {
                    UNPK2(F[0], F[1], PA01b); UNPK2(F[2], F[3], PA23b); F[4] = PA4b;
                    UNPK2(F[5], F[6], PB01b); UNPK2(F[7], F[8], PB23b); F[9] = PB4b;
                    const size_t ob1 = (size_t)t1 * bstr + (size_t)rowB * C_OUT;
#pragma unroll
                    for (int c = 0; c < C_OUT; ++c) {
                        const float cur2 = __fadd_rn(F[c], rb2[c]);
                        float m2 = mem2B[c];
                        const float r2 = (m2 > THR) ? 1.0f : 0.0f;
                        m2 = __fsub_rn(fmaf(BETA, m2, cur2), r2);
                        mem2B[c] = m2;
                        out[ob1 + c]          = (m2 > THR) ? 1.0f : 0.0f;
                        out[memoff + ob1 + c] = m2;
                    }
                    if (hasB) {
                        const size_t ob2 = ob1 + bstr;
#pragma unroll
                        for (int c = 0; c < C_OUT; ++c) {
                            const float cur2 = __fadd_rn(F[5 + c], rb2[c]);
                            float m2 = mem2B[c];
                            const float r2 = (m2 > THR) ? 1.0f : 0.0f;
                            m2 = __fsub_rn(fmaf(BETA, m2, cur2), r2);
                            mem2B[c] = m2;
                            out[ob2 + c]          = (m2 > THR) ? 1.0f : 0.0f;
                            out[memoff + ob2 + c] = m2;
                        }
                    }
                }
            }
        }
    }
}

extern "C" void kernel_launch(void* const* d_in, const int* in_sizes, int n_in,
                              void* d_out, int out_size)
{
    const float* x  = (const float*)d_in[0];
    const float* W1 = (const float*)d_in[1];
    const float* b1 = (const float*)d_in[2];
    const float* W2 = (const float*)d_in[3];
    const float* b2 = (const float*)d_in[4];
    float* out = (float*)d_out;

    const int B = in_sizes[0] / D_IN;
    const int steps = (int)((long long)out_size / (2LL * B * C_OUT));

    cudaFuncSetAttribute(snn_fused_kernel,
                         cudaFuncAttributeMaxDynamicSharedMemorySize, SMEM_BYTES);

    const int grid = (B + RPB - 1) / RPB;
    snn_fused_kernel<<<grid, TPB, SMEM_BYTES>>>(x, W1, b1, W2, b2, out, B, steps);
}

// round 17
// speedup vs baseline: 1.0410x; 1.0410x over previous
#include <cuda_runtime.h>

#define D_IN   187
#define H_HID  50
#define C_OUT  5
#define LPR    4            // lanes per row-group
#define HP     13           // h per lane (52 padded)
#define TPB    128
#define RPB    64           // rows per block (2 rows per lane group)
#define DCH    48           // d-chunk (4 chunks: 48*3 + 43)
#define SXP    52           // sx row pitch: 16B-aligned, bases mod 32 distinct
#define THR    1.0f
#define BETA   0.9f

typedef unsigned long long u64;

// packed f32x2 helpers (two independent RN fp32 ops -> bit-identical to scalar)
#define FMA2(acc, s, w) asm("fma.rn.f32x2 %0, %1, %2, %0;" : "+l"(acc) : "l"(s), "l"(w))
#define DUP2(d, f)      asm("mov.b64 %0, {%1, %1};" : "=l"(d) : "f"(f))
#define UNPK2(lo, hi, d) asm("mov.b64 {%0, %1}, %2;" : "=f"(lo), "=f"(hi) : "l"(d))

// Shared layout (floats):
//  sW1: [dloc][j*20+i] pitch 80/d; lane 128b bases {0,20,8,28} mod 32 conflict-free
//  sW2: [h][8] (h padded to 52); per-hh 16B loads at h*32B -> conflict-free
//  sx : [r][SXP], r in 0..63
#define SM_W1   0
#define SM_W1_SZ (DCH * 80)              // 3840
#define SM_W2   (SM_W1 + SM_W1_SZ)
#define SM_W2_SZ (52 * 8)                // 416
#define SM_X    (SM_W2 + SM_W2_SZ)
#define SM_X_SZ (RPB * SXP)              // 3328
#define SMEM_BYTES ((SM_X + SM_X_SZ) * 4)   // 30336 B -> 6 blocks/SM by smem

__global__ __launch_bounds__(TPB, 5)
void snn_fused_kernel(const float* __restrict__ x,
                      const float* __restrict__ W1,
                      const float* __restrict__ b1,
                      const float* __restrict__ W2,
                      const float* __restrict__ b2,
                      float* __restrict__ out,
                      int B, int steps)
{
    extern __shared__ float smem[];
    float* sW1 = smem + SM_W1;
    float* sW2 = smem + SM_W2;
    float* sx  = smem + SM_X;

    const int tid   = threadIdx.x;
    const int j     = tid & (LPR - 1);
    const int rloc  = tid >> 2;                 // 0..31
    const int rowA  = blockIdx.x * RPB + rloc;
    const int rowB  = rowA + 32;
    const bool vA   = (rowA < B);
    const bool vB   = (rowB < B);
    const int hbase = j * HP;

    // ---- stage W2 [h][8], h>=50 zero ----
    for (int idx = tid; idx < 52 * C_OUT; idx += TPB) {
        int h = idx % 52, c = idx / 52;
        sW2[h * 8 + c] = (h < H_HID) ? W2[c * H_HID + h] : 0.0f;
    }

    // ---- phase 1: cur1 for BOTH rows; exact ascending-k fma chains (f32x2) ----
    u64 A01a = 0, A23a = 0, A45a = 0, A67a = 0, A89a = 0, Aaba = 0;
    u64 A01b = 0, A23b = 0, A45b = 0, A67b = 0, A89b = 0, Aabb = 0;
    float a12a = 0.0f, a12b = 0.0f;

    for (int d0 = 0; d0 < D_IN; d0 += DCH) {
        const int len = (D_IN - d0 < DCH) ? (D_IN - d0) : DCH;
        __syncthreads();
        for (int idx = tid; idx < 52 * len; idx += TPB) {
            int h = idx % 52, dloc = idx / 52;
            float v = (h < H_HID) ? W1[h * D_IN + d0 + dloc] : 0.0f;
            sW1[dloc * 80 + (h / HP) * 20 + (h % HP)] = v;
        }
        for (int i2 = tid; i2 < RPB * len; i2 += TPB) {
            int r  = i2 / len;
            int dl = i2 - r * len;
            int gr = blockIdx.x * RPB + r;
            sx[r * SXP + dl] = (gr < B) ? x[(size_t)gr * D_IN + d0 + dl] : 0.0f;
        }
        __syncthreads();
        const float* xA = &sx[rloc * SXP];
        const float* xB = &sx[(rloc + 32) * SXP];
        const float* wbase = &sW1[j * 20];

#define GEMM_BODY(XVA, XVB, DL) do {                                      \
            const float* wp = wbase + (DL) * 80;                          \
            ulonglong2 wA = *(const ulonglong2*)(wp);                     \
            ulonglong2 wB = *(const ulonglong2*)(wp + 4);                 \
            ulonglong2 wC = *(const ulonglong2*)(wp + 8);                 \
            float w12 = wp[12];                                           \
            u64 xda; DUP2(xda, (XVA));                                    \
            u64 xdb; DUP2(xdb, (XVB));                                    \
            FMA2(A01a, xda, wA.x); FMA2(A23a, xda, wA.y);                 \
            FMA2(A45a, xda, wB.x); FMA2(A67a, xda, wB.y);                 \
            FMA2(A89a, xda, wC.x); FMA2(Aaba, xda, wC.y);                 \
            a12a = fmaf(w12, (XVA), a12a);                                \
            FMA2(A01b, xdb, wA.x); FMA2(A23b, xdb, wA.y);                 \
            FMA2(A45b, xdb, wB.x); FMA2(A67b, xdb, wB.y);                 \
            FMA2(A89b, xdb, wC.x); FMA2(Aabb, xdb, wC.y);                 \
            a12b = fmaf(w12, (XVB), a12b);                                \
        } while (0)

        const int q4 = len >> 2;
        const float4* xqA = (const float4*)xA;
        const float4* xqB = (const float4*)xB;
        for (int g = 0; g < q4; ++g) {
            float4 va = xqA[g];
            float4 vb = xqB[g];
            GEMM_BODY(va.x, vb.x, 4 * g + 0);
            GEMM_BODY(va.y, vb.y, 4 * g + 1);
            GEMM_BODY(va.z, vb.z, 4 * g + 2);
            GEMM_BODY(va.w, vb.w, 4 * g + 3);
        }
        for (int dl = q4 * 4; dl < len; ++dl) {
            GEMM_BODY(xA[dl], xB[dl], dl);
        }
#undef GEMM_BODY
    }

    // unpack; bias as separate rounded add; pad h -> 0
    float cur1A[HP], cur1B[HP];
    UNPK2(cur1A[0],  cur1A[1],  A01a); UNPK2(cur1A[2],  cur1A[3],  A23a);
    UNPK2(cur1A[4],  cur1A[5],  A45a); UNPK2(cur1A[6],  cur1A[7],  A67a);
    UNPK2(cur1A[8],  cur1A[9],  A89a); UNPK2(cur1A[10], cur1A[11], Aaba);
    cur1A[12] = a12a;
    UNPK2(cur1B[0],  cur1B[1],  A01b); UNPK2(cur1B[2],  cur1B[3],  A23b);
    UNPK2(cur1B[4],  cur1B[5],  A45b); UNPK2(cur1B[6],  cur1B[7],  A67b);
    UNPK2(cur1B[8],  cur1B[9],  A89b); UNPK2(cur1B[10], cur1B[11], Aabb);
    cur1B[12] = a12b;
#pragma unroll
    for (int i = 0; i < HP; ++i) {
        int h = hbase + i;
        cur1A[i] = (h < H_HID) ? __fadd_rn(cur1A[i], b1[h]) : 0.0f;
        cur1B[i] = (h < H_HID) ? __fadd_rn(cur1B[i], b1[h]) : 0.0f;
    }

    // ---- phase 2: pair-relay over 2 rows. Lane j handles pair p = i - j
    // (t = 2p, 2p+1) for BOTH rows -> 2x independent work per thread (ILP).
    // Each t's 50-term cur2 chain stays exactly serial across lanes (shfl
    // relay). W2 via shared, 2 LDS per hh per hop serving 20 FMAs.
    // Inner form: FSEL + spike-as-FMA-multiplier (fma pipe; R6/R16 showed
    // predication lands on the alu pipe and regresses).
    float m1A[HP], m1B[HP];
#pragma unroll
    for (int i = 0; i < HP; ++i) { m1A[i] = 0.0f; m1B[i] = 0.0f; }

    u64 PA01a = 0, PA23a = 0, PB01a = 0, PB23a = 0;   // row A, steps t1/t2
    u64 PA01b = 0, PA23b = 0, PB01b = 0, PB23b = 0;   // row B
    float PA4a = 0, PB4a = 0, PA4b = 0, PB4b = 0;

    float mem2A[C_OUT], mem2B[C_OUT], rb2[C_OUT];
#pragma unroll
    for (int c = 0; c < C_OUT; ++c) { mem2A[c] = 0.0f; mem2B[c] = 0.0f; rb2[c] = b2[c]; }

    const size_t memoff = (size_t)steps * B * C_OUT;
    const size_t bstr   = (size_t)B * C_OUT;
    const int npairs = (steps + 1) >> 1;
    const int iters  = npairs + LPR - 1;
    const bool storer = (j == LPR - 1);
    const float* w2p = &sW2[hbase * 8];

    for (int i = 0; i < iters; ++i) {
        u64 qA01a = __shfl_up_sync(0xFFFFFFFFu, PA01a, 1, LPR);
        u64 qA23a = __shfl_up_sync(0xFFFFFFFFu, PA23a, 1, LPR);
        u64 qB01a = __shfl_up_sync(0xFFFFFFFFu, PB01a, 1, LPR);
        u64 qB23a = __shfl_up_sync(0xFFFFFFFFu, PB23a, 1, LPR);
        float qA4a = __shfl_up_sync(0xFFFFFFFFu, PA4a, 1, LPR);
        float qB4a = __shfl_up_sync(0xFFFFFFFFu, PB4a, 1, LPR);
        u64 qA01b = __shfl_up_sync(0xFFFFFFFFu, PA01b, 1, LPR);
        u64 qA23b = __shfl_up_sync(0xFFFFFFFFu, PA23b, 1, LPR);
        u64 qB01b = __shfl_up_sync(0xFFFFFFFFu, PB01b, 1, LPR);
        u64 qB23b = __shfl_up_sync(0xFFFFFFFFu, PB23b, 1, LPR);
        float qA4b = __shfl_up_sync(0xFFFFFFFFu, PA4b, 1, LPR);
        float qB4b = __shfl_up_sync(0xFFFFFFFFu, PB4b, 1, LPR);

        const int p = i - j;
        if ((unsigned)p < (unsigned)npairs) {
            const bool z = (j == 0);
            u64 aA01a = z ? 0 : qA01a, aA23a = z ? 0 : qA23a;
            u64 aB01a = z ? 0 : qB01a, aB23a = z ? 0 : qB23a;
            u64 aA01b = z ? 0 : qA01b, aA23b = z ? 0 : qA23b;
            u64 aB01b = z ? 0 : qB01b, aB23b = z ? 0 : qB23b;
            float aA4a = z ? 0.0f : qA4a, aB4a = z ? 0.0f : qB4a;
            float aA4b = z ? 0.0f : qA4b, aB4b = z ? 0.0f : qB4b;

#pragma unroll
            for (int hh = 0; hh < HP; ++hh) {
                const ulonglong2 wp2 = *(const ulonglong2*)(w2p + hh * 8);
                const float w4 = w2p[hh * 8 + 4];
                // row A
                {
                    const float mo = m1A[hh], c1 = cur1A[hh];
                    const float r0 = (mo > THR) ? 1.0f : 0.0f;
                    const float m1 = __fsub_rn(fmaf(BETA, mo, c1), r0);
                    const float s1 = (m1 > THR) ? 1.0f : 0.0f;
                    const float m2 = __fsub_rn(fmaf(BETA, m1, c1), s1);
                    m1A[hh] = m2;
                    const float s2 = (m2 > THR) ? 1.0f : 0.0f;
                    u64 s1d; DUP2(s1d, s1);
                    u64 s2d; DUP2(s2d, s2);
                    FMA2(aA01a, s1d, wp2.x); FMA2(aA23a, s1d, wp2.y);
                    aA4a = fmaf(s1, w4, aA4a);
                    FMA2(aB01a, s2d, wp2.x); FMA2(aB23a, s2d, wp2.y);
                    aB4a = fmaf(s2, w4, aB4a);
                }
                // row B
                {
                    const float mo = m1B[hh], c1 = cur1B[hh];
                    const float r0 = (mo > THR) ? 1.0f : 0.0f;
                    const float m1 = __fsub_rn(fmaf(BETA, mo, c1), r0);
                    const float s1 = (m1 > THR) ? 1.0f : 0.0f;
                    const float m2 = __fsub_rn(fmaf(BETA, m1, c1), s1);
                    m1B[hh] = m2;
                    const float s2 = (m2 > THR) ? 1.0f : 0.0f;
                    u64 s1d; DUP2(s1d, s1);
                    u64 s2d; DUP2(s2d, s2);
                    FMA2(aA01b, s1d, wp2.x); FMA2(aA23b, s1d, wp2.y);
                    aA4b = fmaf(s1, w4, aA4b);
                    FMA2(aB01b, s2d, wp2.x); FMA2(aB23b, s2d, wp2.y);
                    aB4b = fmaf(s2, w4, aB4b);
                }
            }
            PA01a = aA01a; PA23a = aA23a; PB01a = aB01a; PB23a = aB23a;
            PA4a = aA4a; PB4a = aB4a;
            PA01b = aA01b; PA23b = aA23b; PB01b = aB01b; PB23b = aB23b;
            PA4b = aA4b; PB4b = aB4b;

            if (storer) {
                const int t1 = 2 * p;
                const int t2 = t1 + 1;
                const bool hasB = (t2 < steps);
                float F[2 * C_OUT];

                if (vA) {
                    UNPK2(F[0], F[1], PA01a); UNPK2(F[2], F[3], PA23a); F[4] = PA4a;
                    UNPK2(F[5], F[6], PB01a); UNPK2(F[7], F[8], PB23a); F[9] = PB4a;
                    const size_t ob1 = (size_t)t1 * bstr + (size_t)rowA * C_OUT;
#pragma unroll
                    for (int c = 0; c < C_OUT; ++c) {
                        const float cur2 = __fadd_rn(F[c], rb2[c]);
                        float m2 = mem2A[c];
                        const float r2 = (m2 > THR) ? 1.0f : 0.0f;
                        m2 = __fsub_rn(fmaf(BETA, m2, cur2), r2);
                        mem2A[c] = m2;
                        out[ob1 + c]          = (m2 > THR) ? 1.0f : 0.0f;
                        out[memoff + ob1 + c] = m2;
                    }
                    if (hasB) {
                        const size_t ob2 = ob1 + bstr;
#pragma unroll
                        for (int c = 0; c < C_OUT; ++c) {
                            const float cur2 = __fadd_rn(F[5 + c], rb2[c]);
                            float m2 = mem2A[c];
                            const float r2 = (m2 > THR) ? 1.0f : 0.0f;
                            m2 = __fsub_rn(fmaf(BETA, m2, cur2), r2);
                            mem2A[c] = m2;
                            out[ob2 + c]          = (m2 > THR) ? 1.0f : 0.0f;
                            out[memoff + ob2 + c] = m2;
                        }
                    }
                }
                if (vB) {
                    UNPK2(F[0], F[1], PA01b); UNPK2(F[2], F[3], PA23b); F[4] = PA4b;
                    UNPK2(F[5], F[6], PB01b); UNPK2(F[7], F[8], PB23b); F[9] = PB4b;
                    const size_t ob1 = (size_t)t1 * bstr + (size_t)rowB * C_OUT;
#pragma unroll
                    for (int c = 0; c < C_OUT; ++c) {
                        const float cur2 = __fadd_rn(F[c], rb2[c]);
                        float m2 = mem2B[c];
                        const float r2 = (m2 > THR) ? 1.0f : 0.0f;
                        m2 = __fsub_rn(fmaf(BETA, m2, cur2), r2);
                        mem2B[c] = m2;
                        out[ob1 + c]          = (m2 > THR) ? 1.0f : 0.0f;
                        out[memoff + ob1 + c] = m2;
                    }
                    if (hasB) {
                        const size_t ob2 = ob1 + bstr;
#pragma unroll
                        for (int c = 0; c < C_OUT; ++c) {
                            const float cur2 = __fadd_rn(F[5 + c], rb2[c]);
                            float m2 = mem2B[c];
                            const float r2 = (m2 > THR) ? 1.0f : 0.0f;
                            m2 = __fsub_rn(fmaf(BETA, m2, cur2), r2);
                            mem2B[c] = m2;
                            out[ob2 + c]          = (m2 > THR) ? 1.0f : 0.0f;
                            out[memoff + ob2 + c] = m2;
                        }
                    }
                }
            }
        }
    }
}

extern "C" void kernel_launch(void* const* d_in, const int* in_sizes, int n_in,
                              void* d_out, int out_size)
{
    const float* x  = (const float*)d_in[0];
    const float* W1 = (const float*)d_in[1];
    const float* b1 = (const float*)d_in[2];
    const float* W2 = (const float*)d_in[3];
    const float* b2 = (const float*)d_in[4];
    float* out = (float*)d_out;

    const int B = in_sizes[0] / D_IN;
    const int steps = (int)((long long)out_size / (2LL * B * C_OUT));

    cudaFuncSetAttribute(snn_fused_kernel,
                         cudaFuncAttributeMaxDynamicSharedMemorySize, SMEM_BYTES);

    const int grid = (B + RPB - 1) / RPB;
    snn_fused_kernel<<<grid, TPB, SMEM_BYTES>>>(x, W1, b1, W2, b2, out, B, steps);
}